// round 2
// baseline (speedup 1.0000x reference)
#include <cuda_runtime.h>
#include <cuda_bf16.h>
#include <cstdint>

// Problem constants (fixed by the reference)
#define PN   64      // batch
#define PL   2048    // sequence length
#define PC   256     // timestep channels
#define PDEM 10
#define PCO  276     // output channels = 256 + 20
#define SSEG 16      // segments along L
#define SEGL (PL / SSEG)   // 128

// Scratch (allocation-free: __device__ globals)
__device__ float g_dem_emb[PN * 20];
__device__ float g_prefix_sum[PN * SSEG * PC];
__device__ float g_prefix_cnt[PN * SSEG * PC];
__device__ int   g_flags[PN * SSEG];

// ---------------------------------------------------------------------------
// Kernel 0: reset chain flags + compute dem MLP (Linear10->40, ReLU, 40->20, ReLU)
// ---------------------------------------------------------------------------
__global__ void prep_kernel(const float* __restrict__ dem,
                            const float* __restrict__ W1,
                            const float* __restrict__ b1,
                            const float* __restrict__ W2,
                            const float* __restrict__ b2) {
    int tid = blockIdx.x * blockDim.x + threadIdx.x;
    if (tid < PN * SSEG) g_flags[tid] = 0;
    if (tid < PN) {
        float d[PDEM];
        #pragma unroll
        for (int k = 0; k < PDEM; k++) d[k] = dem[tid * PDEM + k];
        float h[40];
        #pragma unroll
        for (int j = 0; j < 40; j++) {
            float a = b1[j];
            #pragma unroll
            for (int k = 0; k < PDEM; k++) a = fmaf(d[k], W1[k * 40 + j], a);
            h[j] = fmaxf(a, 0.0f);
        }
        #pragma unroll
        for (int j = 0; j < 20; j++) {
            float a = b2[j];
            #pragma unroll
            for (int k = 0; k < 40; k++) a = fmaf(h[k], W2[k * 20 + j], a);
            g_dem_emb[tid * 20 + j] = fmaxf(a, 0.0f);
        }
    }
}

// ---------------------------------------------------------------------------
// Kernel 1: chained segmented scan.
// Grid (SSEG, PN), 256 threads; thread t owns channel t of its (n, segment).
// Phase 1: local (sum, nonzero-count) aggregate over the 128 L-steps.
// Chain:   wait for predecessor's inclusive prefix via flag, publish ours.
// Phase 2: re-read segment (L2 hit), emit relu(cumsum / max(cumcnt,1)).
// The 20 dem channels are constant along L -> broadcast store.
// ---------------------------------------------------------------------------
__global__ void __launch_bounds__(256)
scan_kernel(const float* __restrict__ ts, float* __restrict__ out) {
    const int s = blockIdx.x;       // segment
    const int n = blockIdx.y;       // patient
    const int t = threadIdx.x;      // channel 0..255

    const float* base = ts + ((size_t)n * PL + (size_t)s * SEGL) * PC + t;

    // Phase 1: local aggregate
    float sum = 0.0f, cnt = 0.0f;
    #pragma unroll 8
    for (int i = 0; i < SEGL; i++) {
        float v = base[(size_t)i * PC];
        sum += v;
        cnt += (v != 0.0f) ? 1.0f : 0.0f;
    }

    const int idx = n * SSEG + s;
    float pre_s = 0.0f, pre_c = 0.0f;
    if (s > 0) {
        if (t == 0) {
            // predecessor has strictly smaller linear block id -> no deadlock
            while (atomicAdd(&g_flags[idx - 1], 0) == 0) { __nanosleep(64); }
        }
        __syncthreads();
        __threadfence();
        pre_s = __ldcg(&g_prefix_sum[(idx - 1) * PC + t]);
        pre_c = __ldcg(&g_prefix_cnt[(idx - 1) * PC + t]);
    }
    if (s < SSEG - 1) {
        __stcg(&g_prefix_sum[idx * PC + t], pre_s + sum);
        __stcg(&g_prefix_cnt[idx * PC + t], pre_c + cnt);
        __threadfence();
        __syncthreads();   // all 256 channels published before flag set
        if (t == 0) atomicExch(&g_flags[idx], 1);
    }

    // Phase 2: streamed output
    const float dv = (t < 20) ? g_dem_emb[n * 20 + t] : 0.0f;
    float rs = pre_s, rc = pre_c;
    float* ob = out + ((size_t)n * PL + (size_t)s * SEGL) * PCO;
    #pragma unroll 8
    for (int i = 0; i < SEGL; i++) {
        float v = base[(size_t)i * PC];
        rs += v;
        rc += (v != 0.0f) ? 1.0f : 0.0f;
        float o = fmaxf(rs / fmaxf(rc, 1.0f), 0.0f);
        ob[(size_t)i * PCO + t] = o;
        if (t < 20) ob[(size_t)i * PCO + PC + t] = dv;
    }
}

// ---------------------------------------------------------------------------
// kernel_launch: prep (flags + dem MLP) then the chained scan. Graph-capturable,
// allocation-free, deterministic.
// Inputs (metadata order): timesteps(64,2048,256) f32, dem(64,10) f32,
//   W1(10,40) f32, b1(40) f32, W2(40,20) f32, b2(20) f32.
// Output: (64,2048,276) f32.
// ---------------------------------------------------------------------------
extern "C" void kernel_launch(void* const* d_in, const int* in_sizes, int n_in,
                              void* d_out, int out_size) {
    const float* ts  = (const float*)d_in[0];
    const float* dem = (const float*)d_in[1];
    const float* W1  = (const float*)d_in[2];
    const float* b1  = (const float*)d_in[3];
    const float* W2  = (const float*)d_in[4];
    const float* b2  = (const float*)d_in[5];
    float* out = (float*)d_out;

    prep_kernel<<<4, 256>>>(dem, W1, b1, W2, b2);
    dim3 grid(SSEG, PN);
    scan_kernel<<<grid, 256>>>(ts, out);
}

// round 4
// speedup vs baseline: 1.2680x; 1.2680x over previous
#include <cuda_runtime.h>
#include <cuda_bf16.h>
#include <cstdint>

// Problem constants (fixed by the reference)
#define PN   64      // batch
#define PL   2048    // sequence length
#define PC   256     // timestep channels
#define PDEM 10
#define PCO  276     // output channels = 256 + 20
#define SSEG 16      // segments along L
#define SEGL (PL / SSEG)   // 128

// Scratch (allocation-free: __device__ globals)
__device__ float g_dem_emb[PN * 20];
__device__ float g_recip[PL + 1];          // 1/max(k,1) for k = 0..2048
__device__ float g_prefix_sum[PN * SSEG * PC];
__device__ int   g_prefix_cnt[PN * SSEG * PC];
__device__ int   g_flags[PN * SSEG];

// ---------------------------------------------------------------------------
// Kernel 0: reset chain flags + reciprocal table + dem MLP
// (Linear 10->40, ReLU, 40->20, ReLU). Launched with 12*256 = 3072 threads.
// ---------------------------------------------------------------------------
__global__ void prep_kernel(const float* __restrict__ dem,
                            const float* __restrict__ W1,
                            const float* __restrict__ b1,
                            const float* __restrict__ W2,
                            const float* __restrict__ b2) {
    int tid = blockIdx.x * blockDim.x + threadIdx.x;
    if (tid <= PL) g_recip[tid] = 1.0f / (float)max(tid, 1);
    if (tid < PN * SSEG) g_flags[tid] = 0;
    if (tid < PN) {
        float d[PDEM];
        #pragma unroll
        for (int k = 0; k < PDEM; k++) d[k] = dem[tid * PDEM + k];
        float h[40];
        #pragma unroll
        for (int j = 0; j < 40; j++) {
            float a = b1[j];
            #pragma unroll
            for (int k = 0; k < PDEM; k++) a = fmaf(d[k], W1[k * 40 + j], a);
            h[j] = fmaxf(a, 0.0f);
        }
        #pragma unroll
        for (int j = 0; j < 20; j++) {
            float a = b2[j];
            #pragma unroll
            for (int k = 0; k < 40; k++) a = fmaf(h[k], W2[k * 20 + j], a);
            g_dem_emb[tid * 20 + j] = fmaxf(a, 0.0f);
        }
    }
}

// ---------------------------------------------------------------------------
// Kernel 1: chained segmented scan, division-free.
// Grid (SSEG, PN), 256 threads; thread t owns channel t of its (n, segment).
// Phase 1: local (sum, nonzero-count) aggregate over the 128 L-steps.
// Chain:   wait for predecessor's inclusive prefix via flag, publish ours.
// Phase 2: re-read segment, emit relu(cumsum * recip[cumcnt]) via smem table.
// The 20 dem channels are constant along L -> coalesced epilogue store.
// ---------------------------------------------------------------------------
__global__ void __launch_bounds__(256)
scan_kernel(const float* __restrict__ ts, float* __restrict__ out) {
    const int s = blockIdx.x;       // segment
    const int n = blockIdx.y;       // patient
    const int t = threadIdx.x;      // channel 0..255

    __shared__ float s_recip[PL + 1];
    __shared__ float s_dem[20];

    // Fill smem reciprocal table + dem embedding (L2-resident after wave 1)
    for (int k = t; k <= PL; k += 256) s_recip[k] = g_recip[k];
    if (t < 20) s_dem[t] = g_dem_emb[n * 20 + t];

    const float* base = ts + ((size_t)n * PL + (size_t)s * SEGL) * PC + t;

    // Phase 1: local aggregate
    float sum = 0.0f;
    int   cnt = 0;
    #pragma unroll 8
    for (int i = 0; i < SEGL; i++) {
        float v = base[(size_t)i * PC];
        sum += v;
        cnt += (v != 0.0f) ? 1 : 0;
    }

    const int idx = n * SSEG + s;
    float pre_s = 0.0f;
    int   pre_c = 0;
    if (s > 0) {
        if (t == 0) {
            // predecessor has strictly smaller linear block id -> no deadlock;
            // plain L2-coherent poll (flag written via atomicExch after fence)
            volatile int* fl = &g_flags[idx - 1];
            while (*fl == 0) { __nanosleep(64); }
        }
        __syncthreads();
        __threadfence();
        pre_s = __ldcg(&g_prefix_sum[(idx - 1) * PC + t]);
        pre_c = __ldcg(&g_prefix_cnt[(idx - 1) * PC + t]);
    }
    if (s < SSEG - 1) {
        __stcg(&g_prefix_sum[idx * PC + t], pre_s + sum);
        __stcg(&g_prefix_cnt[idx * PC + t], pre_c + cnt);
        __threadfence();
        __syncthreads();   // all 256 channels published before flag set
        if (t == 0) atomicExch(&g_flags[idx], 1);
    }
    __syncthreads();       // smem table ready before phase 2

    // Phase 2: streamed output, division-free (LDS table lookup)
    float rs = pre_s;
    int   rc = pre_c;
    float* ob = out + ((size_t)n * PL + (size_t)s * SEGL) * PCO;
    #pragma unroll 4
    for (int i = 0; i < SEGL; i++) {
        float v = base[(size_t)i * PC];
        rs += v;
        rc += (v != 0.0f) ? 1 : 0;
        float o = fmaxf(rs * s_recip[rc], 0.0f);
        ob[(size_t)i * PCO + t] = o;
    }

    // Epilogue: dem channels (constant along L, relu(const>=0)=const)
    for (int j = t; j < 20 * SEGL; j += 256) {
        int row = j / 20;
        int c   = j - row * 20;
        ob[(size_t)row * PCO + PC + c] = s_dem[c];
    }
}

// ---------------------------------------------------------------------------
// kernel_launch: prep (flags + table + dem MLP) then the chained scan.
// Graph-capturable, allocation-free, deterministic.
// Inputs (metadata order): timesteps(64,2048,256) f32, dem(64,10) f32,
//   W1(10,40) f32, b1(40) f32, W2(40,20) f32, b2(20) f32.
// Output: (64,2048,276) f32.
// ---------------------------------------------------------------------------
extern "C" void kernel_launch(void* const* d_in, const int* in_sizes, int n_in,
                              void* d_out, int out_size) {
    const float* ts  = (const float*)d_in[0];
    const float* dem = (const float*)d_in[1];
    const float* W1  = (const float*)d_in[2];
    const float* b1  = (const float*)d_in[3];
    const float* W2  = (const float*)d_in[4];
    const float* b2  = (const float*)d_in[5];
    float* out = (float*)d_out;

    prep_kernel<<<12, 256>>>(dem, W1, b1, W2, b2);
    dim3 grid(SSEG, PN);
    scan_kernel<<<grid, 256>>>(ts, out);
}